// round 1
// baseline (speedup 1.0000x reference)
#include <cuda_runtime.h>
#include <cuda_bf16.h>
#include <math.h>

// InnerCos: mean over rows of clamp(1 - cos_sim(x_i, centers[label_i]))
// x: [N, 256] f32, label: [N] i32, centers: [C, 256] f32 -> scalar f32

#define D_DIM 256
#define THREADS 512          // 16 warps
#define ITERS 16             // rows per warp
#define ROWS_PER_BLOCK (16 * ITERS)   // 256

__global__ void __launch_bounds__(THREADS)
inner_cos_kernel(const float* __restrict__ x,
                 const int* __restrict__ lab,
                 const float* __restrict__ cen,
                 float* __restrict__ out,
                 int N, int C, float invN)
{
    extern __shared__ float sc[];   // C * 256 floats (normalized centers)

    const int tid  = threadIdx.x;
    const int lane = tid & 31;
    const int warp = tid >> 5;

    // ---- Stage centers into smem (vectorized, coalesced) ----
    {
        const int total4 = (C * D_DIM) / 4;
        const float4* src = reinterpret_cast<const float4*>(cen);
        float4* dst = reinterpret_cast<float4*>(sc);
        for (int i = tid; i < total4; i += THREADS)
            dst[i] = src[i];
    }
    __syncthreads();

    // ---- Normalize each center row in place: c <- c * rsqrt(sum c^2) ----
    for (int r = warp; r < C; r += (THREADS / 32)) {
        float4* row = reinterpret_cast<float4*>(sc + r * D_DIM);
        float4 v0 = row[lane];
        float4 v1 = row[lane + 32];
        float s = v0.x*v0.x + v0.y*v0.y + v0.z*v0.z + v0.w*v0.w
                + v1.x*v1.x + v1.y*v1.y + v1.z*v1.z + v1.w*v1.w;
        #pragma unroll
        for (int o = 16; o > 0; o >>= 1)
            s += __shfl_xor_sync(0xffffffffu, s, o);
        float inv = rsqrtf(s);
        v0.x *= inv; v0.y *= inv; v0.z *= inv; v0.w *= inv;
        v1.x *= inv; v1.y *= inv; v1.z *= inv; v1.w *= inv;
        row[lane] = v0;
        row[lane + 32] = v1;
    }
    __syncthreads();

    // ---- Main loop: one warp per row ----
    float acc = 0.0f;   // valid on lane 0 only
    const int row_base = blockIdx.x * ROWS_PER_BLOCK + warp;

    #pragma unroll 4
    for (int it = 0; it < ITERS; ++it) {
        const int r = row_base + it * (THREADS / 32);
        if (r < N) {
            const int lb = __ldg(lab + r);
            const float4* xr = reinterpret_cast<const float4*>(x + (size_t)r * D_DIM);
            const float4* cr = reinterpret_cast<const float4*>(sc + lb * D_DIM);

            float4 a0 = __ldg(xr + lane);
            float4 a1 = __ldg(xr + lane + 32);
            float4 c0 = cr[lane];
            float4 c1 = cr[lane + 32];

            float dot = a0.x*c0.x + a0.y*c0.y + a0.z*c0.z + a0.w*c0.w
                      + a1.x*c1.x + a1.y*c1.y + a1.z*c1.z + a1.w*c1.w;
            float nx2 = a0.x*a0.x + a0.y*a0.y + a0.z*a0.z + a0.w*a0.w
                      + a1.x*a1.x + a1.y*a1.y + a1.z*a1.z + a1.w*a1.w;

            #pragma unroll
            for (int o = 16; o > 0; o >>= 1) {
                dot += __shfl_xor_sync(0xffffffffu, dot, o);
                nx2 += __shfl_xor_sync(0xffffffffu, nx2, o);
            }

            if (lane == 0) {
                // cos = dot(x, c/||c||) / ||x||  ==  dot/(||x||*||c||)
                float cos = dot * rsqrtf(fmaxf(nx2, 1e-30f));
                float d = 1.0f - cos;
                d = fminf(fmaxf(d, 1e-12f), 1e12f);
                acc += d;
            }
        }
    }

    // ---- Block reduction + single atomic per block ----
    __shared__ float wsum[THREADS / 32];
    if (lane == 0) wsum[warp] = acc;
    __syncthreads();
    if (tid == 0) {
        float s = 0.0f;
        #pragma unroll
        for (int i = 0; i < THREADS / 32; ++i) s += wsum[i];
        atomicAdd(out, s * invN);
    }
}

extern "C" void kernel_launch(void* const* d_in, const int* in_sizes, int n_in,
                              void* d_out, int out_size)
{
    const float* x   = (const float*)d_in[0];   // ref_emb [N, 256]
    const int*   lab = (const int*)d_in[1];     // ref_label [N]
    const float* cen = (const float*)d_in[2];   // centers [C, 256]
    float* out = (float*)d_out;

    const int N = in_sizes[1];
    const int C = in_sizes[2] / D_DIM;
    const size_t smem = (size_t)C * D_DIM * sizeof(float);

    static bool attr_set = false;
    if (!attr_set) {
        cudaFuncSetAttribute(inner_cos_kernel,
                             cudaFuncAttributeMaxDynamicSharedMemorySize,
                             (int)smem);
        attr_set = true;
    }

    cudaMemsetAsync(d_out, 0, sizeof(float), 0);

    const int blocks = (N + ROWS_PER_BLOCK - 1) / ROWS_PER_BLOCK;
    inner_cos_kernel<<<blocks, THREADS, smem>>>(x, lab, cen, out, N, C,
                                                1.0f / (float)N);
}

// round 2
// speedup vs baseline: 1.1394x; 1.1394x over previous
#include <cuda_runtime.h>
#include <cuda_bf16.h>
#include <math.h>

// InnerCos: mean over rows of clamp(1 - cos_sim(x_i, centers[label_i]))
// x: [N, 256] f32, label: [N] i32, centers: [C, 256] f32 -> scalar f32

#define D_DIM 256
#define THREADS 512               // 16 warps
#define ITERS 16                  // rows per warp
#define ROWS_PER_BLOCK (16 * ITERS)   // 256

__device__ float g_inv_cnorm[1024];   // 1/||centers[c]||, C <= 1024

// ---- Prologue: one warp per center computes inverse norm ----
__global__ void center_norm_kernel(const float* __restrict__ cen, int C)
{
    const int c    = blockIdx.x;
    const int lane = threadIdx.x;
    const float4* row = reinterpret_cast<const float4*>(cen + (size_t)c * D_DIM);
    float4 v0 = __ldg(row + lane);
    float4 v1 = __ldg(row + lane + 32);
    float s = v0.x*v0.x + v0.y*v0.y + v0.z*v0.z + v0.w*v0.w
            + v1.x*v1.x + v1.y*v1.y + v1.z*v1.z + v1.w*v1.w;
    #pragma unroll
    for (int o = 16; o > 0; o >>= 1)
        s += __shfl_xor_sync(0xffffffffu, s, o);
    if (lane == 0)
        g_inv_cnorm[c] = rsqrtf(fmaxf(s, 1e-30f));
}

// ---- Main: warp per row, centers served from L1, no smem ----
__global__ void __launch_bounds__(THREADS)
inner_cos_kernel(const float* __restrict__ x,
                 const int* __restrict__ lab,
                 const float* __restrict__ cen,
                 float* __restrict__ out,
                 int N, float invN)
{
    const int tid  = threadIdx.x;
    const int lane = tid & 31;
    const int warp = tid >> 5;
    const int nwarps = THREADS / 32;

    float acc = 0.0f;   // valid on lane 0 only
    const int row_base = blockIdx.x * ROWS_PER_BLOCK + warp;

    #pragma unroll
    for (int it = 0; it < ITERS; it += 2) {
        const int rA = row_base + (it + 0) * nwarps;
        const int rB = row_base + (it + 1) * nwarps;
        const bool vA = rA < N;
        const bool vB = rB < N;

        // --- issue ALL global loads for both rows up front (max MLP) ---
        int lbA = 0, lbB = 0;
        float4 aA0, aA1, aB0, aB1;
        if (vA) {
            lbA = __ldg(lab + rA);
            const float4* xr = reinterpret_cast<const float4*>(x + (size_t)rA * D_DIM);
            aA0 = __ldg(xr + lane);
            aA1 = __ldg(xr + lane + 32);
        }
        if (vB) {
            lbB = __ldg(lab + rB);
            const float4* xr = reinterpret_cast<const float4*>(x + (size_t)rB * D_DIM);
            aB0 = __ldg(xr + lane);
            aB1 = __ldg(xr + lane + 32);
        }
        float4 cA0, cA1, cB0, cB1;
        if (vA) {
            const float4* cr = reinterpret_cast<const float4*>(cen + (size_t)lbA * D_DIM);
            cA0 = __ldg(cr + lane);
            cA1 = __ldg(cr + lane + 32);
        }
        if (vB) {
            const float4* cr = reinterpret_cast<const float4*>(cen + (size_t)lbB * D_DIM);
            cB0 = __ldg(cr + lane);
            cB1 = __ldg(cr + lane + 32);
        }

        // --- math ---
        float dotA = 0.f, nxA = 0.f, dotB = 0.f, nxB = 0.f;
        if (vA) {
            dotA = aA0.x*cA0.x + aA0.y*cA0.y + aA0.z*cA0.z + aA0.w*cA0.w
                 + aA1.x*cA1.x + aA1.y*cA1.y + aA1.z*cA1.z + aA1.w*cA1.w;
            nxA  = aA0.x*aA0.x + aA0.y*aA0.y + aA0.z*aA0.z + aA0.w*aA0.w
                 + aA1.x*aA1.x + aA1.y*aA1.y + aA1.z*aA1.z + aA1.w*aA1.w;
        }
        if (vB) {
            dotB = aB0.x*cB0.x + aB0.y*cB0.y + aB0.z*cB0.z + aB0.w*cB0.w
                 + aB1.x*cB1.x + aB1.y*cB1.y + aB1.z*cB1.z + aB1.w*cB1.w;
            nxB  = aB0.x*aB0.x + aB0.y*aB0.y + aB0.z*aB0.z + aB0.w*aB0.w
                 + aB1.x*aB1.x + aB1.y*aB1.y + aB1.z*aB1.z + aB1.w*aB1.w;
        }

        // --- interleaved butterfly reductions (independent chains) ---
        #pragma unroll
        for (int o = 16; o > 0; o >>= 1) {
            dotA += __shfl_xor_sync(0xffffffffu, dotA, o);
            dotB += __shfl_xor_sync(0xffffffffu, dotB, o);
            nxA  += __shfl_xor_sync(0xffffffffu, nxA, o);
            nxB  += __shfl_xor_sync(0xffffffffu, nxB, o);
        }

        if (lane == 0) {
            if (vA) {
                float cos = dotA * g_inv_cnorm[lbA] * rsqrtf(fmaxf(nxA, 1e-30f));
                acc += fminf(fmaxf(1.0f - cos, 1e-12f), 1e12f);
            }
            if (vB) {
                float cos = dotB * g_inv_cnorm[lbB] * rsqrtf(fmaxf(nxB, 1e-30f));
                acc += fminf(fmaxf(1.0f - cos, 1e-12f), 1e12f);
            }
        }
    }

    // ---- Block reduction + single atomic per block ----
    __shared__ float wsum[THREADS / 32];
    if (lane == 0) wsum[warp] = acc;
    __syncthreads();
    if (tid == 0) {
        float s = 0.0f;
        #pragma unroll
        for (int i = 0; i < THREADS / 32; ++i) s += wsum[i];
        atomicAdd(out, s * invN);
    }
}

extern "C" void kernel_launch(void* const* d_in, const int* in_sizes, int n_in,
                              void* d_out, int out_size)
{
    const float* x   = (const float*)d_in[0];   // ref_emb [N, 256]
    const int*   lab = (const int*)d_in[1];     // ref_label [N]
    const float* cen = (const float*)d_in[2];   // centers [C, 256]
    float* out = (float*)d_out;

    const int N = in_sizes[1];
    const int C = in_sizes[2] / D_DIM;

    cudaMemsetAsync(d_out, 0, sizeof(float), 0);

    center_norm_kernel<<<C, 32>>>(cen, C);

    const int blocks = (N + ROWS_PER_BLOCK - 1) / ROWS_PER_BLOCK;
    inner_cos_kernel<<<blocks, THREADS>>>(x, lab, cen, out, N, 1.0f / (float)N);
}